// round 15
// baseline (speedup 1.0000x reference)
#include <cuda_runtime.h>
#include <cuda_fp16.h>
#include <cstdint>

#define V  32000
#define SQ 256
#define BQ 16
#define HQ 16
#define MT 4096            // rows = SQ*BQ
#define TT 10              // B tiles per CTA
#define NBY 25             // grid.y (NBY*TT = 250 tiles of 128)
#define KD 32              // fp16 direct K
#define LOG2E 1.4426950408889634f
#define EXP_OFS 14.0f      // fp16 exponent rebias

// ---------------- scratch (__device__ globals; no allocs) -------------------
__device__ float g_xproj[2 * SQ * BQ * HQ];
__device__ __half g_Ah[MT * KD];                 // A for pass 2 (plain)
__device__ __half g_A2[MT * KD];                 // A for pass 1 (x log2e)
__device__ __half g_Bh[(size_t)V * KD];
__device__ float g_part[(size_t)NBY * MT];

__device__ __forceinline__ uint32_t smem_u32(const void* p) {
    uint32_t a;
    asm("{ .reg .u64 t; cvta.to.shared.u64 t, %1; cvt.u32.u64 %0, t; }" : "=r"(a) : "l"(p));
    return a;
}
__device__ __forceinline__ void ldsm_x4(uint32_t* r, uint32_t addr) {
    asm volatile("ldmatrix.sync.aligned.m8n8.x4.shared.b16 {%0,%1,%2,%3}, [%4];"
                 : "=r"(r[0]), "=r"(r[1]), "=r"(r[2]), "=r"(r[3]) : "r"(addr));
}
__device__ __forceinline__ void mma16816(float* c, const uint32_t* a, uint32_t b0, uint32_t b1) {
    asm volatile("mma.sync.aligned.m16n8k16.row.col.f32.f16.f16.f32 "
                 "{%0,%1,%2,%3}, {%4,%5,%6,%7}, {%8,%9}, {%0,%1,%2,%3};"
                 : "+f"(c[0]), "+f"(c[1]), "+f"(c[2]), "+f"(c[3])
                 : "r"(a[0]), "r"(a[1]), "r"(a[2]), "r"(a[3]), "r"(b0), "r"(b1));
}
__device__ __forceinline__ void stcs2(float* p, float x, float y) {
    asm volatile("st.global.cs.v2.f32 [%0], {%1,%2};" :: "l"(p), "f"(x), "f"(y) : "memory");
}
__device__ __forceinline__ __half2 h2exp2_(__half2 x) {
    uint32_t xi = *(uint32_t*)&x, ri;
    asm("ex2.approx.f16x2 %0, %1;" : "=r"(ri) : "r"(xi));
    return *(__half2*)&ri;
}
__device__ __forceinline__ float tanh_fast(float x) {
    float r;
    asm("tanh.approx.f32 %0, %1;" : "=f"(r) : "f"(x));
    return r;
}

// ---------------------------------------------------------------------------
__global__ void xproj_kernel(const int* __restrict__ tok, const float* __restrict__ emb,
                             const float* __restrict__ W_lr, const float* __restrict__ b_lr,
                             const float* __restrict__ W_rl, const float* __restrict__ b_rl) {
    int idx = blockIdx.x * blockDim.x + threadIdx.x;
    if (idx >= 2 * SQ * BQ * HQ) return;
    int h = idx & 15, b = (idx >> 4) & 15, s = (idx >> 8) & 255, dir = idx >> 16;
    const float* W = dir ? W_rl : W_lr;
    const float* bb = dir ? b_rl : b_lr;
    int t = tok[s * BQ + b];
    float acc = bb[h];
    const float* erow = emb + (size_t)t * 32;
#pragma unroll
    for (int e = 0; e < 32; e++) acc = fmaf(erow[e], W[e * HQ + h], acc);
    g_xproj[idx] = acc;
}

// Fused: blocks 0..15 run the RNN scan (1 warp each); blocks 16.. run prepB.
__global__ void rnn_prepB_kernel(const float* __restrict__ mask_lr, const float* __restrict__ mask_rl,
                                 const float* __restrict__ W_lr, const float* __restrict__ W_rl,
                                 const float* __restrict__ h0p, const float* __restrict__ Who) {
    if (blockIdx.x >= 16) {
        int idx = (blockIdx.x - 16) * 256 + threadIdx.x;
        int n = idx >> 5, k = idx & 31;
        g_Bh[(size_t)n * KD + k] = __float2half_rn(Who[k * V + n]);
        return;
    }
    if (threadIdx.x >= 32) return;

    const int b = blockIdx.x, lane = threadIdx.x;
    const bool rl = lane >= 16;
    const int h = lane & 15;
    const unsigned grpbase = lane & 16;
    const int off = rl ? 16 : 0;
    const float* W = rl ? W_rl : W_lr;
    const float* mask = rl ? mask_rl : mask_lr;
    const float* xp = g_xproj + (rl ? SQ * BQ * HQ : 0);
    float Wh[16];
#pragma unroll
    for (int j = 0; j < 16; j++) Wh[j] = W[(32 + j) * HQ + h];
    float hv = h0p[h];
    {
        int row = rl ? ((SQ - 1) * BQ + b) : b;
        g_Ah[row * 32 + off + h] = __float2half_rn(hv);
        g_A2[row * 32 + off + h] = __float2half_rn(hv * LOG2E);
    }
    int s0 = rl ? (SQ - 1) : 0;
    float xv = xp[(s0 * BQ + b) * HQ + h];
    float mv = mask[(s0 * BQ + b) * HQ + h];
    for (int t = 0; t < SQ; t++) {
        int s = rl ? (SQ - 1 - t) : t;
        float xn = 0.f, mn = 0.f;
        if (t < SQ - 1) {
            int sn = rl ? (s - 1) : (s + 1);
            xn = xp[(sn * BQ + b) * HQ + h];
            mn = mask[(sn * BQ + b) * HQ + h];
        }
        float acc0 = xv, acc1 = 0.f, acc2 = 0.f, acc3 = 0.f;
#pragma unroll
        for (int j = 0; j < 4; j++) {
            float h0 = __shfl_sync(0xffffffffu, hv, grpbase + j);
            float h1 = __shfl_sync(0xffffffffu, hv, grpbase + 4 + j);
            float h2 = __shfl_sync(0xffffffffu, hv, grpbase + 8 + j);
            float h3 = __shfl_sync(0xffffffffu, hv, grpbase + 12 + j);
            acc0 = fmaf(Wh[j], h0, acc0);
            acc1 = fmaf(Wh[4 + j], h1, acc1);
            acc2 = fmaf(Wh[8 + j], h2, acc2);
            acc3 = fmaf(Wh[12 + j], h3, acc3);
        }
        hv = tanh_fast((acc0 + acc1) + (acc2 + acc3)) * (mv * (1.0f / 0.6f));
        int srow = -1;
        if (!rl) { if (s < SQ - 1) srow = (s + 1) * BQ + b; }
        else     { if (s > 0)      srow = (s - 1) * BQ + b; }
        if (srow >= 0) {
            g_Ah[srow * 32 + off + h] = __float2half_rn(hv);
            g_A2[srow * 32 + off + h] = __float2half_rn(hv * LOG2E);
        }
        xv = xn; mv = mn;
    }
}

// ---------------------------------------------------------------------------
// GEMM: CTA = 128 rows x (TT=10 tiles of 128 cols), 256 thr, warps 4(M)x2(N).
// A staged once; B tiles double-buffered (prefetch overlaps MMA).
// PASS 1 (log2 domain, +14 rebias): exp via ex2.f16x2, half2 per-tile accum.
// PASS 2: lse computed in-prologue (fused, redundant per y-CTA), normalize,
// streaming store.
// ---------------------------------------------------------------------------
static constexpr int TSTR = 40;

template <int PASS>
__global__ void __launch_bounds__(256, 2)
gemm_kernel(const float* __restrict__ bho, float* __restrict__ out) {
    __shared__ __align__(16) __half As[128 * TSTR];
    __shared__ __align__(16) __half Bs[2][128 * TSTR];
    __shared__ float s_bias[2][128];
    __shared__ float s_red[256];       // pass1 reduction / pass2 lse values

    const int tid = threadIdx.x, w = tid >> 5, l = tid & 31;
    const int wm = w & 3, wn = w >> 2;
    const int g = l >> 2, tg = l & 3;
    const int m0 = blockIdx.x * 128;
    const int nb0 = blockIdx.y * TT;

    const int lr = tid >> 2, lu = tid & 3;
    {
        const __half* Asrc = (PASS == 1) ? g_A2 : g_Ah;
        const uint4* Ag = (const uint4*)(Asrc + (size_t)m0 * KD);
        uint4* As4 = (uint4*)As;
        As4[lr * 5 + lu] = Ag[tid];
        As4[(lr + 64) * 5 + lu] = Ag[tid + 256];
        const uint4* Bg = (const uint4*)(g_Bh + (size_t)nb0 * 128 * KD);
        uint4* Bs4 = (uint4*)Bs[0];
        Bs4[lr * 5 + lu] = Bg[tid];
        Bs4[(lr + 64) * 5 + lu] = Bg[tid + 256];
        if (tid < 128) s_bias[0][tid] = bho[nb0 * 128 + tid];
    }
    if (PASS == 2) {
        // fused lse: each CTA computes the 128 lse values of its row block
        if (tid < 128) {
            float s = 0.f;
#pragma unroll
            for (int cc = 0; cc < NBY; cc++) s += g_part[(size_t)cc * MT + m0 + tid];
            s_red[tid] = 16.f + logf(s);
        }
    }
    __syncthreads();

    const uint32_t aB = smem_u32(As);
    const int j = l >> 3, r8 = l & 7;
    const uint32_t aRow = (uint32_t)(wm * 32 + (j & 1) * 8 + r8);
    const uint32_t aColJ = (uint32_t)((j >> 1) * 8);
    const uint32_t bRowOff = 2u * (uint32_t)((wn * 64 + (j >> 1) * 8 + r8) * TSTR + (j & 1) * 8);

    uint32_t afrag[2][2][4];
#pragma unroll
    for (int kt = 0; kt < 2; kt++)
#pragma unroll
        for (int mt = 0; mt < 2; mt++)
            ldsm_x4(afrag[kt][mt], aB + 2u * ((aRow + mt * 16) * TSTR + kt * 16 + aColJ));

    float lse[2][2];
    if (PASS == 2) {
        const int rb = wm * 32 + g;
#pragma unroll
        for (int mt = 0; mt < 2; mt++) {
            lse[mt][0] = s_red[rb + mt * 16];
            lse[mt][1] = s_red[rb + mt * 16 + 8];
        }
    }

    float sums[2][2] = {{0.f, 0.f}, {0.f, 0.f}};

#pragma unroll
    for (int t = 0; t < TT; t++) {
        const int cur = t & 1, nxt = cur ^ 1;
        const int n0 = (nb0 + t) * 128;
        if (t + 1 < TT) {
            const uint4* Bg = (const uint4*)(g_Bh + (size_t)(n0 + 128) * KD);
            uint4 v0 = Bg[tid], v1 = Bg[tid + 256];
            float bv = (tid < 128) ? bho[n0 + 128 + tid] : 0.f;
            uint4* Bs4 = (uint4*)Bs[nxt];
            Bs4[lr * 5 + lu] = v0;
            Bs4[(lr + 64) * 5 + lu] = v1;
            if (tid < 128) s_bias[nxt][tid] = bv;
        }

        float c[2][8][4];
#pragma unroll
        for (int nt = 0; nt < 8; nt++) {
            int cb = wn * 64 + nt * 8 + 2 * tg;
            float b0v = (PASS == 1) ? (s_bias[cur][cb] - 16.f) * LOG2E + EXP_OFS : s_bias[cur][cb];
            float b1v = (PASS == 1) ? (s_bias[cur][cb + 1] - 16.f) * LOG2E + EXP_OFS : s_bias[cur][cb + 1];
#pragma unroll
            for (int mt = 0; mt < 2; mt++) {
                c[mt][nt][0] = b0v; c[mt][nt][1] = b1v;
                c[mt][nt][2] = b0v; c[mt][nt][3] = b1v;
            }
        }

        const uint32_t bBc = smem_u32(Bs[cur]) + bRowOff;
#pragma unroll
        for (int kt = 0; kt < 2; kt++) {
#pragma unroll
            for (int p = 0; p < 4; p++) {
                uint32_t b[4];
                ldsm_x4(b, bBc + 2u * (uint32_t)(p * 16 * TSTR + kt * 16));
                mma16816(c[0][2 * p],     afrag[kt][0], b[0], b[1]);
                mma16816(c[1][2 * p],     afrag[kt][1], b[0], b[1]);
                mma16816(c[0][2 * p + 1], afrag[kt][0], b[2], b[3]);
                mma16816(c[1][2 * p + 1], afrag[kt][1], b[2], b[3]);
            }
        }

        if (PASS == 1) {
            __half2 hs[2][2];
#pragma unroll
            for (int mt = 0; mt < 2; mt++)
#pragma unroll
                for (int hf = 0; hf < 2; hf++) hs[mt][hf] = __half2half2(__ushort_as_half(0));
#pragma unroll
            for (int mt = 0; mt < 2; mt++)
#pragma unroll
                for (int nt = 0; nt < 8; nt++) {
                    hs[mt][0] = __hadd2(hs[mt][0], h2exp2_(__floats2half2_rn(c[mt][nt][0], c[mt][nt][1])));
                    hs[mt][1] = __hadd2(hs[mt][1], h2exp2_(__floats2half2_rn(c[mt][nt][2], c[mt][nt][3])));
                }
#pragma unroll
            for (int mt = 0; mt < 2; mt++)
#pragma unroll
                for (int hf = 0; hf < 2; hf++) {
                    float2 f = __half22float2(hs[mt][hf]);
                    sums[mt][hf] += f.x + f.y;
                }
        } else {
            const int rbase = m0 + wm * 32 + g;
            float* r0 = out + (size_t)(rbase) * V + n0 + wn * 64 + 2 * tg;
#pragma unroll
            for (int mt = 0; mt < 2; mt++) {
                float* q0 = r0 + (size_t)(mt * 16) * V;
                float* q1 = q0 + 8 * V;
#pragma unroll
                for (int nt = 0; nt < 8; nt++) {
                    stcs2(q0 + nt * 8, c[mt][nt][0] - lse[mt][0], c[mt][nt][1] - lse[mt][0]);
                    stcs2(q1 + nt * 8, c[mt][nt][2] - lse[mt][1], c[mt][nt][3] - lse[mt][1]);
                }
            }
        }
        __syncthreads();
    }

    if (PASS == 1) {
#pragma unroll
        for (int mt = 0; mt < 2; mt++)
#pragma unroll
            for (int hf = 0; hf < 2; hf++) {
                float v = sums[mt][hf];
                v += __shfl_xor_sync(0xffffffffu, v, 1);
                v += __shfl_xor_sync(0xffffffffu, v, 2);
                if (tg == 0) s_red[w * 32 + mt * 16 + hf * 8 + g] = v;
            }
        __syncthreads();
        if (tid < 128)
            g_part[(size_t)blockIdx.y * MT + m0 + tid] =
                (s_red[tid] + s_red[128 + tid]) * 0x1p-14f;
    }
}

// ---------------------------------------------------------------------------
extern "C" void kernel_launch(void* const* d_in, const int* in_sizes, int n_in,
                              void* d_out, int out_size) {
    const int*   tok     = (const int*)  d_in[0];
    const float* mask_lr = (const float*)d_in[1];
    const float* mask_rl = (const float*)d_in[2];
    const float* emb     = (const float*)d_in[3];
    const float* W_lr    = (const float*)d_in[4];
    const float* b_lr    = (const float*)d_in[5];
    const float* W_rl    = (const float*)d_in[6];
    const float* b_rl    = (const float*)d_in[7];
    const float* W_ho    = (const float*)d_in[8];
    const float* b_ho    = (const float*)d_in[9];
    const float* h0      = (const float*)d_in[10];
    float* out = (float*)d_out;

    xproj_kernel<<<512, 256>>>(tok, emb, W_lr, b_lr, W_rl, b_rl);
    rnn_prepB_kernel<<<16 + 4000, 256>>>(mask_lr, mask_rl, W_lr, W_rl, h0, W_ho);
    gemm_kernel<1><<<dim3(32, NBY), 256>>>(b_ho, out);
    gemm_kernel<2><<<dim3(32, NBY), 256>>>(b_ho, out);
}

// round 16
// speedup vs baseline: 1.0993x; 1.0993x over previous
#include <cuda_runtime.h>
#include <cuda_fp16.h>
#include <cstdint>

#define V  32000
#define SQ 256
#define BQ 16
#define HQ 16
#define MT 4096            // rows = SQ*BQ
#define TT 5               // B tiles per CTA
#define NBY 50             // grid.y (NBY*TT = 250 tiles of 128)
#define KD 32              // fp16 direct K
#define LOG2E 1.4426950408889634f
#define EXP_OFS 14.0f      // fp16 exponent rebias

// ---------------- scratch (__device__ globals; no allocs) -------------------
__device__ float g_xproj[2 * SQ * BQ * HQ];
__device__ __half g_Ah[MT * KD];                 // A for pass 2 (plain)
__device__ __half g_A2[MT * KD];                 // A for pass 1 (x log2e)
__device__ __half g_Bh[(size_t)V * KD];
__device__ float g_part[(size_t)NBY * MT];
__device__ float g_lse[MT];

__device__ __forceinline__ uint32_t smem_u32(const void* p) {
    uint32_t a;
    asm("{ .reg .u64 t; cvta.to.shared.u64 t, %1; cvt.u32.u64 %0, t; }" : "=r"(a) : "l"(p));
    return a;
}
__device__ __forceinline__ void ldsm_x4(uint32_t* r, uint32_t addr) {
    asm volatile("ldmatrix.sync.aligned.m8n8.x4.shared.b16 {%0,%1,%2,%3}, [%4];"
                 : "=r"(r[0]), "=r"(r[1]), "=r"(r[2]), "=r"(r[3]) : "r"(addr));
}
__device__ __forceinline__ void mma16816(float* c, const uint32_t* a, uint32_t b0, uint32_t b1) {
    asm volatile("mma.sync.aligned.m16n8k16.row.col.f32.f16.f16.f32 "
                 "{%0,%1,%2,%3}, {%4,%5,%6,%7}, {%8,%9}, {%0,%1,%2,%3};"
                 : "+f"(c[0]), "+f"(c[1]), "+f"(c[2]), "+f"(c[3])
                 : "r"(a[0]), "r"(a[1]), "r"(a[2]), "r"(a[3]), "r"(b0), "r"(b1));
}
__device__ __forceinline__ void stcs4(float* p, float4 v) {
    asm volatile("st.global.cs.v4.f32 [%0], {%1,%2,%3,%4};"
                 :: "l"(p), "f"(v.x), "f"(v.y), "f"(v.z), "f"(v.w) : "memory");
}
__device__ __forceinline__ __half2 h2exp2_(__half2 x) {
    uint32_t xi = *(uint32_t*)&x, ri;
    asm("ex2.approx.f16x2 %0, %1;" : "=r"(ri) : "r"(xi));
    return *(__half2*)&ri;
}
__device__ __forceinline__ float tanh_fast(float x) {
    float r;
    asm("tanh.approx.f32 %0, %1;" : "=f"(r) : "f"(x));
    return r;
}

// ---------------------------------------------------------------------------
__global__ void xproj_kernel(const int* __restrict__ tok, const float* __restrict__ emb,
                             const float* __restrict__ W_lr, const float* __restrict__ b_lr,
                             const float* __restrict__ W_rl, const float* __restrict__ b_rl) {
    int idx = blockIdx.x * blockDim.x + threadIdx.x;
    if (idx >= 2 * SQ * BQ * HQ) return;
    int h = idx & 15, b = (idx >> 4) & 15, s = (idx >> 8) & 255, dir = idx >> 16;
    const float* W = dir ? W_rl : W_lr;
    const float* bb = dir ? b_rl : b_lr;
    int t = tok[s * BQ + b];
    float acc = bb[h];
    const float* erow = emb + (size_t)t * 32;
#pragma unroll
    for (int e = 0; e < 32; e++) acc = fmaf(erow[e], W[e * HQ + h], acc);
    g_xproj[idx] = acc;
}

// Fused: blocks 0..15 run the RNN scan (1 warp each); blocks 16.. run prepB.
__global__ void rnn_prepB_kernel(const float* __restrict__ mask_lr, const float* __restrict__ mask_rl,
                                 const float* __restrict__ W_lr, const float* __restrict__ W_rl,
                                 const float* __restrict__ h0p, const float* __restrict__ Who) {
    if (blockIdx.x >= 16) {
        int idx = (blockIdx.x - 16) * 256 + threadIdx.x;
        int n = idx >> 5, k = idx & 31;
        g_Bh[(size_t)n * KD + k] = __float2half_rn(Who[k * V + n]);
        return;
    }
    if (threadIdx.x >= 32) return;

    const int b = blockIdx.x, lane = threadIdx.x;
    const bool rl = lane >= 16;
    const int h = lane & 15;
    const unsigned grpbase = lane & 16;
    const int off = rl ? 16 : 0;
    const float* W = rl ? W_rl : W_lr;
    const float* mask = rl ? mask_rl : mask_lr;
    const float* xp = g_xproj + (rl ? SQ * BQ * HQ : 0);
    float Wh[16];
#pragma unroll
    for (int j = 0; j < 16; j++) Wh[j] = W[(32 + j) * HQ + h];
    float hv = h0p[h];
    {
        int row = rl ? ((SQ - 1) * BQ + b) : b;
        g_Ah[row * 32 + off + h] = __float2half_rn(hv);
        g_A2[row * 32 + off + h] = __float2half_rn(hv * LOG2E);
    }
    int s0 = rl ? (SQ - 1) : 0;
    float xv = xp[(s0 * BQ + b) * HQ + h];
    float mv = mask[(s0 * BQ + b) * HQ + h];
    for (int t = 0; t < SQ; t++) {
        int s = rl ? (SQ - 1 - t) : t;
        float xn = 0.f, mn = 0.f;
        if (t < SQ - 1) {
            int sn = rl ? (s - 1) : (s + 1);
            xn = xp[(sn * BQ + b) * HQ + h];
            mn = mask[(sn * BQ + b) * HQ + h];
        }
        float acc0 = xv, acc1 = 0.f, acc2 = 0.f, acc3 = 0.f;
#pragma unroll
        for (int j = 0; j < 4; j++) {
            float h0 = __shfl_sync(0xffffffffu, hv, grpbase + j);
            float h1 = __shfl_sync(0xffffffffu, hv, grpbase + 4 + j);
            float h2 = __shfl_sync(0xffffffffu, hv, grpbase + 8 + j);
            float h3 = __shfl_sync(0xffffffffu, hv, grpbase + 12 + j);
            acc0 = fmaf(Wh[j], h0, acc0);
            acc1 = fmaf(Wh[4 + j], h1, acc1);
            acc2 = fmaf(Wh[8 + j], h2, acc2);
            acc3 = fmaf(Wh[12 + j], h3, acc3);
        }
        hv = tanh_fast((acc0 + acc1) + (acc2 + acc3)) * (mv * (1.0f / 0.6f));
        int srow = -1;
        if (!rl) { if (s < SQ - 1) srow = (s + 1) * BQ + b; }
        else     { if (s > 0)      srow = (s - 1) * BQ + b; }
        if (srow >= 0) {
            g_Ah[srow * 32 + off + h] = __float2half_rn(hv);
            g_A2[srow * 32 + off + h] = __float2half_rn(hv * LOG2E);
        }
        xv = xn; mv = mn;
    }
}

// ---------------------------------------------------------------------------
// GEMM: CTA = 128 rows x (TT=5 tiles of 128 cols), 256 thr, warps 4(M)x2(N).
// A staged once; B tiles double-buffered (prefetch overlaps MMA).
// PASS 1 (log2 domain, +14 rebias): exp via ex2.f16x2, half2 per-tile accum.
// PASS 2: normalize; warp-private smem transpose -> coalesced st.cs.v4.
// ---------------------------------------------------------------------------
static constexpr int TSTR = 40;

template <int PASS>
__global__ void __launch_bounds__(256, 2)
gemm_kernel(const float* __restrict__ bho, float* __restrict__ out) {
    __shared__ __align__(16) __half As[128 * TSTR];
    __shared__ __align__(16) __half Bs[2][128 * TSTR];
    __shared__ float s_bias[2][128];
    __shared__ float s_red[256];
    __shared__ __align__(16) float stage[PASS == 2 ? 8 * 16 * 32 : 4];  // 16KB (pass2)

    const int tid = threadIdx.x, w = tid >> 5, l = tid & 31;
    const int wm = w & 3, wn = w >> 2;
    const int g = l >> 2, tg = l & 3;
    const int m0 = blockIdx.x * 128;
    const int nb0 = blockIdx.y * TT;

    const int lr = tid >> 2, lu = tid & 3;
    {
        const __half* Asrc = (PASS == 1) ? g_A2 : g_Ah;
        const uint4* Ag = (const uint4*)(Asrc + (size_t)m0 * KD);
        uint4* As4 = (uint4*)As;
        As4[lr * 5 + lu] = Ag[tid];
        As4[(lr + 64) * 5 + lu] = Ag[tid + 256];
        const uint4* Bg = (const uint4*)(g_Bh + (size_t)nb0 * 128 * KD);
        uint4* Bs4 = (uint4*)Bs[0];
        Bs4[lr * 5 + lu] = Bg[tid];
        Bs4[(lr + 64) * 5 + lu] = Bg[tid + 256];
        if (tid < 128) s_bias[0][tid] = bho[nb0 * 128 + tid];
    }
    __syncthreads();

    const uint32_t aB = smem_u32(As);
    const int j = l >> 3, r8 = l & 7;
    const uint32_t aRow = (uint32_t)(wm * 32 + (j & 1) * 8 + r8);
    const uint32_t aColJ = (uint32_t)((j >> 1) * 8);
    const uint32_t bRowOff = 2u * (uint32_t)((wn * 64 + (j >> 1) * 8 + r8) * TSTR + (j & 1) * 8);

    uint32_t afrag[2][2][4];
#pragma unroll
    for (int kt = 0; kt < 2; kt++)
#pragma unroll
        for (int mt = 0; mt < 2; mt++)
            ldsm_x4(afrag[kt][mt], aB + 2u * ((aRow + mt * 16) * TSTR + kt * 16 + aColJ));

    float lse[2][2];
    if (PASS == 2) {
        const int rbase = m0 + wm * 32 + g;
#pragma unroll
        for (int mt = 0; mt < 2; mt++) {
            lse[mt][0] = g_lse[rbase + mt * 16];
            lse[mt][1] = g_lse[rbase + mt * 16 + 8];
        }
    }

    float sums[2][2] = {{0.f, 0.f}, {0.f, 0.f}};
    float* wst = stage + w * (16 * 32);    // warp-private 2KB stage (pass2)

#pragma unroll
    for (int t = 0; t < TT; t++) {
        const int cur = t & 1, nxt = cur ^ 1;
        const int n0 = (nb0 + t) * 128;
        if (t + 1 < TT) {
            const uint4* Bg = (const uint4*)(g_Bh + (size_t)(n0 + 128) * KD);
            uint4 v0 = Bg[tid], v1 = Bg[tid + 256];
            float bv = (tid < 128) ? bho[n0 + 128 + tid] : 0.f;
            uint4* Bs4 = (uint4*)Bs[nxt];
            Bs4[lr * 5 + lu] = v0;
            Bs4[(lr + 64) * 5 + lu] = v1;
            if (tid < 128) s_bias[nxt][tid] = bv;
        }

        float c[2][8][4];
#pragma unroll
        for (int nt = 0; nt < 8; nt++) {
            int cb = wn * 64 + nt * 8 + 2 * tg;
            float b0v = (PASS == 1) ? (s_bias[cur][cb] - 16.f) * LOG2E + EXP_OFS : s_bias[cur][cb];
            float b1v = (PASS == 1) ? (s_bias[cur][cb + 1] - 16.f) * LOG2E + EXP_OFS : s_bias[cur][cb + 1];
#pragma unroll
            for (int mt = 0; mt < 2; mt++) {
                c[mt][nt][0] = b0v; c[mt][nt][1] = b1v;
                c[mt][nt][2] = b0v; c[mt][nt][3] = b1v;
            }
        }

        const uint32_t bBc = smem_u32(Bs[cur]) + bRowOff;
#pragma unroll
        for (int kt = 0; kt < 2; kt++) {
#pragma unroll
            for (int p = 0; p < 4; p++) {
                uint32_t b[4];
                ldsm_x4(b, bBc + 2u * (uint32_t)(p * 16 * TSTR + kt * 16));
                mma16816(c[0][2 * p],     afrag[kt][0], b[0], b[1]);
                mma16816(c[1][2 * p],     afrag[kt][1], b[0], b[1]);
                mma16816(c[0][2 * p + 1], afrag[kt][0], b[2], b[3]);
                mma16816(c[1][2 * p + 1], afrag[kt][1], b[2], b[3]);
            }
        }

        if (PASS == 1) {
            __half2 hs[2][2];
#pragma unroll
            for (int mt = 0; mt < 2; mt++)
#pragma unroll
                for (int hf = 0; hf < 2; hf++) hs[mt][hf] = __half2half2(__ushort_as_half(0));
#pragma unroll
            for (int mt = 0; mt < 2; mt++)
#pragma unroll
                for (int nt = 0; nt < 8; nt++) {
                    hs[mt][0] = __hadd2(hs[mt][0], h2exp2_(__floats2half2_rn(c[mt][nt][0], c[mt][nt][1])));
                    hs[mt][1] = __hadd2(hs[mt][1], h2exp2_(__floats2half2_rn(c[mt][nt][2], c[mt][nt][3])));
                }
#pragma unroll
            for (int mt = 0; mt < 2; mt++)
#pragma unroll
                for (int hf = 0; hf < 2; hf++) {
                    float2 f = __half22float2(hs[mt][hf]);
                    sums[mt][hf] += f.x + f.y;
                }
        } else {
            // warp-private transpose stage -> coalesced float4 streaming stores
            const int rbase = m0 + wm * 32;
            const int cb0 = n0 + wn * 64;
#pragma unroll
            for (int mt = 0; mt < 2; mt++) {
#pragma unroll
                for (int half = 0; half < 2; half++) {
#pragma unroll
                    for (int q = 0; q < 4; q++) {
                        int nt = half * 4 + q;
                        int col = q * 8 + 2 * tg;                 // 0..31 within half
                        int grp = col >> 2, off = col & 3;
                        int gsw = grp ^ g;                        // XOR swizzle (row&7 == g)
                        *(float2*)&wst[g * 32 + gsw * 4 + off] =
                            make_float2(c[mt][nt][0] - lse[mt][0], c[mt][nt][1] - lse[mt][0]);
                        *(float2*)&wst[(g + 8) * 32 + gsw * 4 + off] =
                            make_float2(c[mt][nt][2] - lse[mt][1], c[mt][nt][3] - lse[mt][1]);
                    }
                    __syncwarp();
#pragma unroll
                    for (int it = 0; it < 4; it++) {
                        int rl_ = (l >> 3) + it * 4;              // 0..15
                        int gsw = (l & 7) ^ (rl_ & 7);
                        float4 v = *(float4*)&wst[rl_ * 32 + gsw * 4];
                        stcs4(out + (size_t)(rbase + mt * 16 + rl_) * V + cb0 + half * 32 + (l & 7) * 4, v);
                    }
                    __syncwarp();
                }
            }
        }
        __syncthreads();
    }

    if (PASS == 1) {
#pragma unroll
        for (int mt = 0; mt < 2; mt++)
#pragma unroll
            for (int hf = 0; hf < 2; hf++) {
                float v = sums[mt][hf];
                v += __shfl_xor_sync(0xffffffffu, v, 1);
                v += __shfl_xor_sync(0xffffffffu, v, 2);
                if (tg == 0) s_red[w * 32 + mt * 16 + hf * 8 + g] = v;
            }
        __syncthreads();
        if (tid < 128)
            g_part[(size_t)blockIdx.y * MT + m0 + tid] =
                (s_red[tid] + s_red[128 + tid]) * 0x1p-14f;
    }
}

__global__ void lse_kernel() {
    int i = blockIdx.x * blockDim.x + threadIdx.x;
    if (i >= MT) return;
    float s = 0.f;
#pragma unroll
    for (int c = 0; c < NBY; c++) s += g_part[(size_t)c * MT + i];
    g_lse[i] = 16.f + logf(s);
}

// ---------------------------------------------------------------------------
extern "C" void kernel_launch(void* const* d_in, const int* in_sizes, int n_in,
                              void* d_out, int out_size) {
    const int*   tok     = (const int*)  d_in[0];
    const float* mask_lr = (const float*)d_in[1];
    const float* mask_rl = (const float*)d_in[2];
    const float* emb     = (const float*)d_in[3];
    const float* W_lr    = (const float*)d_in[4];
    const float* b_lr    = (const float*)d_in[5];
    const float* W_rl    = (const float*)d_in[6];
    const float* b_rl    = (const float*)d_in[7];
    const float* W_ho    = (const float*)d_in[8];
    const float* b_ho    = (const float*)d_in[9];
    const float* h0      = (const float*)d_in[10];
    float* out = (float*)d_out;

    xproj_kernel<<<512, 256>>>(tok, emb, W_lr, b_lr, W_rl, b_rl);
    rnn_prepB_kernel<<<16 + 4000, 256>>>(mask_lr, mask_rl, W_lr, W_rl, h0, W_ho);
    gemm_kernel<1><<<dim3(32, NBY), 256>>>(b_ho, out);
    lse_kernel<<<16, 256>>>();
    gemm_kernel<2><<<dim3(32, NBY), 256>>>(b_ho, out);
}